// round 1
// baseline (speedup 1.0000x reference)
#include <cuda_runtime.h>
#include <math.h>

#define BB 16
#define HH 64
#define WW 64
#define CC 512
#define M_PIX (BB*HH*WW)        // 65536
#define NPROJ 384
#define DK 64                   // C/8
#define DV 256                  // C/2
#define NKV 1024                // pooled pixels per batch
#define NQ  4096                // pixels per batch

// ---------------- scratch (device globals; no runtime allocation) ----------
__device__ float g_proj[M_PIX * NPROJ];      // theta|phi|g full-res projections
__device__ float g_phi[BB * NKV * DK];       // pooled phi
__device__ float g_gv [BB * NKV * DV];       // pooled g
__device__ float g_attng[M_PIX * DV];        // attention output (pre out-proj)
__device__ float g_wcat[CC * NPROJ];
__device__ float g_bcat[NPROJ];

// ---------------- pack weights ----------------
__global__ void pack_kernel(const float* __restrict__ wt, const float* __restrict__ wp,
                            const float* __restrict__ wg, const float* __restrict__ bt,
                            const float* __restrict__ bp, const float* __restrict__ bg) {
    int idx = blockIdx.x * blockDim.x + threadIdx.x;
    if (idx < CC * NPROJ) {
        int k = idx / NPROJ, n = idx - k * NPROJ;
        float v;
        if (n < 64)        v = wt[k * 64 + n];
        else if (n < 128)  v = wp[k * 64 + (n - 64)];
        else               v = wg[k * 256 + (n - 128)];
        g_wcat[idx] = v;
    }
    if (idx < NPROJ) {
        float v;
        if (idx < 64)       v = bt[idx];
        else if (idx < 128) v = bp[idx - 64];
        else                v = bg[idx - 128];
        g_bcat[idx] = v;
    }
}

// ---------------- projection GEMM: proj = X[65536,512] @ Wcat[512,384] + bcat
__global__ void __launch_bounds__(256) proj_gemm(const float* __restrict__ X) {
    __shared__ float As[8][132];
    __shared__ float Bs[8][128];
    int tid = threadIdx.x;
    int row0 = blockIdx.y * 128;
    int n0   = blockIdx.x * 128;
    int tx = tid & 15, ty = tid >> 4;
    int arow = tid >> 1, acol = (tid & 1) * 4;
    int brow = tid >> 5, bcol = (tid & 31) * 4;

    const float* Ap = X + (size_t)(row0 + arow) * CC + acol;
    const float* Bp = g_wcat + (size_t)brow * NPROJ + n0 + bcol;

    float acc[8][8];
#pragma unroll
    for (int i = 0; i < 8; i++)
#pragma unroll
        for (int j = 0; j < 8; j++) acc[i][j] = 0.f;

    for (int k0 = 0; k0 < CC; k0 += 8) {
        float4 a = *(const float4*)(Ap + k0);
        float4 b = *(const float4*)(Bp + (size_t)k0 * NPROJ);
        As[acol + 0][arow] = a.x; As[acol + 1][arow] = a.y;
        As[acol + 2][arow] = a.z; As[acol + 3][arow] = a.w;
        *(float4*)&Bs[brow][bcol] = b;
        __syncthreads();
#pragma unroll
        for (int kk = 0; kk < 8; kk++) {
            float ra[8], rb[8];
            *(float4*)&ra[0] = *(float4*)&As[kk][ty * 4];
            *(float4*)&ra[4] = *(float4*)&As[kk][64 + ty * 4];
            *(float4*)&rb[0] = *(float4*)&Bs[kk][tx * 4];
            *(float4*)&rb[4] = *(float4*)&Bs[kk][64 + tx * 4];
#pragma unroll
            for (int i = 0; i < 8; i++)
#pragma unroll
                for (int j = 0; j < 8; j++)
                    acc[i][j] = fmaf(ra[i], rb[j], acc[i][j]);
        }
        __syncthreads();
    }
#pragma unroll
    for (int ih = 0; ih < 2; ih++)
#pragma unroll
        for (int ii = 0; ii < 4; ii++) {
            int r = row0 + ih * 64 + ty * 4 + ii;
#pragma unroll
            for (int jh = 0; jh < 2; jh++) {
                int c = n0 + jh * 64 + tx * 4;
                float4 o;
                o.x = acc[ih * 4 + ii][jh * 4 + 0] + g_bcat[c + 0];
                o.y = acc[ih * 4 + ii][jh * 4 + 1] + g_bcat[c + 1];
                o.z = acc[ih * 4 + ii][jh * 4 + 2] + g_bcat[c + 2];
                o.w = acc[ih * 4 + ii][jh * 4 + 3] + g_bcat[c + 3];
                *(float4*)&g_proj[(size_t)r * NPROJ + c] = o;
            }
        }
}

// ---------------- 2x2 max pool over phi/g columns of proj ----------------
__global__ void pool_kernel() {
    int item = blockIdx.x * blockDim.x + threadIdx.x;
    const int TOT = BB * NKV * 80;   // 80 float4 of pooled channels per pooled pixel
    if (item >= TOT) return;
    int pp = item / 80, c4 = item - pp * 80;
    int b = pp >> 10;
    int idx = pp & 1023;
    int h2 = idx >> 5, w2 = idx & 31;
    int col = 64 + (c4 << 2);
    int m00 = (b * 64 + h2 * 2) * 64 + w2 * 2;
    float4 v0 = *(const float4*)&g_proj[(size_t)m00 * NPROJ + col];
    float4 v1 = *(const float4*)&g_proj[(size_t)(m00 + 1) * NPROJ + col];
    float4 v2 = *(const float4*)&g_proj[(size_t)(m00 + 64) * NPROJ + col];
    float4 v3 = *(const float4*)&g_proj[(size_t)(m00 + 65) * NPROJ + col];
    float4 mx;
    mx.x = fmaxf(fmaxf(v0.x, v1.x), fmaxf(v2.x, v3.x));
    mx.y = fmaxf(fmaxf(v0.y, v1.y), fmaxf(v2.y, v3.y));
    mx.z = fmaxf(fmaxf(v0.z, v1.z), fmaxf(v2.z, v3.z));
    mx.w = fmaxf(fmaxf(v0.w, v1.w), fmaxf(v2.w, v3.w));
    if (c4 < 16) *(float4*)&g_phi[(size_t)pp * DK + (c4 << 2)]        = mx;
    else         *(float4*)&g_gv [(size_t)pp * DV + ((c4 - 16) << 2)] = mx;
}

// ---------------- flash attention: attn_g = softmax(theta phi^T) g ----------
// Block: 256 threads, 64 queries, stream 16 KV tiles of 64.
#define SM_FLOATS (3*64*68 + 64*256 + 3*64)
__global__ void __launch_bounds__(256) attn_kernel() {
    extern __shared__ float smf[];
    float* theta_s = smf;                 // [64][68]
    float* phi_s   = smf + 64 * 68;       // [64][68]
    float* Ss      = smf + 2 * 64 * 68;   // [64][68]
    float* gs      = smf + 3 * 64 * 68;   // [64][256]
    float* m_i     = gs + 64 * 256;       // [64]
    float* l_i     = m_i + 64;            // [64]
    float* al_s    = l_i + 64;            // [64]

    int tid = threadIdx.x;
    int b = blockIdx.y;
    int mbase = b * NQ + blockIdx.x * 64;

    for (int i = tid; i < 64 * 16; i += 256) {
        int row = i >> 4, c = (i & 15) << 2;
        *(float4*)&theta_s[row * 68 + c] =
            *(const float4*)&g_proj[(size_t)(mbase + row) * NPROJ + c];
    }
    if (tid < 64) { m_i[tid] = -1e30f; l_i[tid] = 0.f; }

    const int q = tid >> 2, r = tid & 3;     // S / softmax mapping
    const int ty = tid >> 4, tx = tid & 15;  // PV mapping

    float4 O[4][4];
#pragma unroll
    for (int i = 0; i < 4; i++)
#pragma unroll
        for (int j = 0; j < 4; j++) O[i][j] = make_float4(0.f, 0.f, 0.f, 0.f);

    for (int kt = 0; kt < 16; kt++) {
        __syncthreads();  // protects phi_s/gs/Ss reuse + init visibility
        int kvbase = b * NKV + kt * 64;
        for (int i = tid; i < 64 * 16; i += 256) {
            int row = i >> 4, c = (i & 15) << 2;
            *(float4*)&phi_s[row * 68 + c] =
                *(const float4*)&g_phi[(size_t)(kvbase + row) * DK + c];
        }
        for (int i = tid; i < 64 * 64; i += 256) {
            *(float4*)&gs[i << 2] = *(const float4*)&g_gv[((size_t)kvbase << 8) + (i << 2)];
        }
        __syncthreads();

        // S[q][k] for k = r + 4*kk
        float acc[16];
#pragma unroll
        for (int kk = 0; kk < 16; kk++) acc[kk] = 0.f;
#pragma unroll
        for (int d4 = 0; d4 < 16; d4++) {
            float4 th = *(float4*)&theta_s[q * 68 + (d4 << 2)];
#pragma unroll
            for (int kk = 0; kk < 16; kk++) {
                float4 ph = *(float4*)&phi_s[(r + (kk << 2)) * 68 + (d4 << 2)];
                acc[kk] += th.x * ph.x + th.y * ph.y + th.z * ph.z + th.w * ph.w;
            }
        }

        // online softmax (4 lanes per row)
        float mt = acc[0];
#pragma unroll
        for (int kk = 1; kk < 16; kk++) mt = fmaxf(mt, acc[kk]);
        mt = fmaxf(mt, __shfl_xor_sync(0xffffffffu, mt, 1));
        mt = fmaxf(mt, __shfl_xor_sync(0xffffffffu, mt, 2));
        float m_old = m_i[q];
        float m_new = fmaxf(m_old, mt);
        float alpha = __expf(m_old - m_new);
        float ls = 0.f;
#pragma unroll
        for (int kk = 0; kk < 16; kk++) {
            float p = __expf(acc[kk] - m_new);
            ls += p;
            Ss[q * 68 + r + (kk << 2)] = p;
        }
        ls += __shfl_xor_sync(0xffffffffu, ls, 1);
        ls += __shfl_xor_sync(0xffffffffu, ls, 2);
        if (r == 0) {
            m_i[q] = m_new;
            l_i[q] = l_i[q] * alpha + ls;
            al_s[q] = alpha;
        }
        __syncthreads();

        // PV: O += P @ g  (thread: rows {ty+16i}, cols {tx*4+64j+e})
        float al[4];
#pragma unroll
        for (int i = 0; i < 4; i++) al[i] = al_s[ty + 16 * i];
#pragma unroll
        for (int i = 0; i < 4; i++)
#pragma unroll
            for (int j = 0; j < 4; j++) {
                O[i][j].x *= al[i]; O[i][j].y *= al[i];
                O[i][j].z *= al[i]; O[i][j].w *= al[i];
            }
        for (int k = 0; k < 64; k++) {
            float sv[4];
#pragma unroll
            for (int i = 0; i < 4; i++) sv[i] = Ss[(ty + 16 * i) * 68 + k];
#pragma unroll
            for (int j = 0; j < 4; j++) {
                float4 gv = *(float4*)&gs[(k << 8) + (tx << 2) + (j << 6)];
#pragma unroll
                for (int i = 0; i < 4; i++) {
                    O[i][j].x = fmaf(sv[i], gv.x, O[i][j].x);
                    O[i][j].y = fmaf(sv[i], gv.y, O[i][j].y);
                    O[i][j].z = fmaf(sv[i], gv.z, O[i][j].z);
                    O[i][j].w = fmaf(sv[i], gv.w, O[i][j].w);
                }
            }
        }
    }

    // epilogue: divide by row sums, write attn_g
#pragma unroll
    for (int i = 0; i < 4; i++) {
        float inv = 1.f / l_i[ty + 16 * i];
        size_t rowoff = (size_t)(mbase + ty + 16 * i) * DV;
#pragma unroll
        for (int j = 0; j < 4; j++) {
            float4 o = O[i][j];
            o.x *= inv; o.y *= inv; o.z *= inv; o.w *= inv;
            *(float4*)&g_attng[rowoff + (tx << 2) + (j << 6)] = o;
        }
    }
}

// ---------------- output GEMM: out = x + sigma*(attn_g @ w_o + b_o) ---------
__global__ void __launch_bounds__(256) out_gemm(const float* __restrict__ X,
                                                const float* __restrict__ Wo,
                                                const float* __restrict__ bo,
                                                const float* __restrict__ sig,
                                                float* __restrict__ out) {
    __shared__ float As[8][132];
    __shared__ float Bs[8][128];
    int tid = threadIdx.x;
    int row0 = blockIdx.y * 128;
    int n0   = blockIdx.x * 128;
    int tx = tid & 15, ty = tid >> 4;
    int arow = tid >> 1, acol = (tid & 1) * 4;
    int brow = tid >> 5, bcol = (tid & 31) * 4;

    const float* Ap = g_attng + (size_t)(row0 + arow) * DV + acol;
    const float* Bp = Wo + (size_t)brow * CC + n0 + bcol;

    float acc[8][8];
#pragma unroll
    for (int i = 0; i < 8; i++)
#pragma unroll
        for (int j = 0; j < 8; j++) acc[i][j] = 0.f;

    for (int k0 = 0; k0 < DV; k0 += 8) {
        float4 a = *(const float4*)(Ap + k0);
        float4 b = *(const float4*)(Bp + (size_t)k0 * CC);
        As[acol + 0][arow] = a.x; As[acol + 1][arow] = a.y;
        As[acol + 2][arow] = a.z; As[acol + 3][arow] = a.w;
        *(float4*)&Bs[brow][bcol] = b;
        __syncthreads();
#pragma unroll
        for (int kk = 0; kk < 8; kk++) {
            float ra[8], rb[8];
            *(float4*)&ra[0] = *(float4*)&As[kk][ty * 4];
            *(float4*)&ra[4] = *(float4*)&As[kk][64 + ty * 4];
            *(float4*)&rb[0] = *(float4*)&Bs[kk][tx * 4];
            *(float4*)&rb[4] = *(float4*)&Bs[kk][64 + tx * 4];
#pragma unroll
            for (int i = 0; i < 8; i++)
#pragma unroll
                for (int j = 0; j < 8; j++)
                    acc[i][j] = fmaf(ra[i], rb[j], acc[i][j]);
        }
        __syncthreads();
    }

    float s = sig[0];
#pragma unroll
    for (int ih = 0; ih < 2; ih++)
#pragma unroll
        for (int ii = 0; ii < 4; ii++) {
            int r = row0 + ih * 64 + ty * 4 + ii;
#pragma unroll
            for (int jh = 0; jh < 2; jh++) {
                int c = n0 + jh * 64 + tx * 4;
                float4 xv = *(const float4*)&X[(size_t)r * CC + c];
                float4 o;
                o.x = xv.x + s * (acc[ih * 4 + ii][jh * 4 + 0] + bo[c + 0]);
                o.y = xv.y + s * (acc[ih * 4 + ii][jh * 4 + 1] + bo[c + 1]);
                o.z = xv.z + s * (acc[ih * 4 + ii][jh * 4 + 2] + bo[c + 2]);
                o.w = xv.w + s * (acc[ih * 4 + ii][jh * 4 + 3] + bo[c + 3]);
                *(float4*)&out[(size_t)r * CC + c] = o;
            }
        }
}

// ---------------- launcher ----------------
extern "C" void kernel_launch(void* const* d_in, const int* in_sizes, int n_in,
                              void* d_out, int out_size) {
    const float* x       = (const float*)d_in[0];
    const float* w_theta = (const float*)d_in[1];
    const float* b_theta = (const float*)d_in[2];
    const float* w_phi   = (const float*)d_in[3];
    const float* b_phi   = (const float*)d_in[4];
    const float* w_g     = (const float*)d_in[5];
    const float* b_g     = (const float*)d_in[6];
    const float* w_o     = (const float*)d_in[7];
    const float* b_o     = (const float*)d_in[8];
    const float* sigma   = (const float*)d_in[9];
    float* out = (float*)d_out;

    pack_kernel<<<(CC * NPROJ + 255) / 256, 256>>>(w_theta, w_phi, w_g,
                                                   b_theta, b_phi, b_g);
    proj_gemm<<<dim3(NPROJ / 128, M_PIX / 128), 256>>>(x);
    pool_kernel<<<(BB * NKV * 80 + 255) / 256, 256>>>();

    const int smem_bytes = SM_FLOATS * (int)sizeof(float);  // 118,272 B
    cudaFuncSetAttribute(attn_kernel, cudaFuncAttributeMaxDynamicSharedMemorySize,
                         smem_bytes);
    attn_kernel<<<dim3(NQ / 64, BB), 256, smem_bytes>>>();

    out_gemm<<<dim3(CC / 128, M_PIX / 128), 256>>>(x, w_o, b_o, sigma, out);
}

// round 3
// speedup vs baseline: 6.0369x; 6.0369x over previous
#include <cuda_runtime.h>
#include <cuda_bf16.h>
#include <cstdint>

#define BBATCH 16
#define CCH 512
#define M_PIX (BBATCH*64*64)     // 65536
#define NPROJ 384
#define DK 64
#define DV 256
#define NKV 1024
#define NQ  4096

// ---------------- scratch (device globals) ----------------
__device__ __align__(256) __nv_bfloat16 g_xb   [M_PIX * CCH];       // x in bf16
__device__ __align__(256) __nv_bfloat16 g_projb[M_PIX * NPROJ];     // theta|phi|g bf16
__device__ __align__(256) __nv_bfloat16 g_phi  [BBATCH * NKV * DK]; // pooled phi [kv][d]
__device__ __align__(256) __nv_bfloat16 g_gT   [BBATCH * DV * NKV]; // pooled g^T [d][kv]
__device__ __align__(256) __nv_bfloat16 g_S    [(size_t)M_PIX * NKV]; // logits -> P
__device__ __align__(256) __nv_bfloat16 g_ag   [M_PIX * DV];        // attn out bf16
__device__ __align__(256) __nv_bfloat16 g_wcatT[NPROJ * CCH];       // proj weights^T
__device__ __align__(256) __nv_bfloat16 g_woT  [CCH * DV];          // w_o^T
__device__ float g_bcat[NPROJ];

// ---------------- helpers ----------------
__device__ __forceinline__ uint32_t smem_u32(const void* p) {
    uint32_t a;
    asm("{ .reg .u64 t; cvta.to.shared.u64 t, %1; cvt.u32.u64 %0, t; }" : "=r"(a) : "l"(p));
    return a;
}
#define SWZ(o) ((o) ^ (((o) >> 3) & 0x70))

__device__ __forceinline__ void ldsm_x4(uint32_t* r, uint32_t a) {
    asm volatile("ldmatrix.sync.aligned.m8n8.x4.shared.b16 {%0,%1,%2,%3}, [%4];"
        : "=r"(r[0]), "=r"(r[1]), "=r"(r[2]), "=r"(r[3]) : "r"(a));
}
__device__ __forceinline__ void mma16816(float* d, const uint32_t* a, uint32_t b0, uint32_t b1) {
    asm volatile("mma.sync.aligned.m16n8k16.row.col.f32.bf16.bf16.f32 "
        "{%0,%1,%2,%3}, {%4,%5,%6,%7}, {%8,%9}, {%0,%1,%2,%3};"
        : "+f"(d[0]), "+f"(d[1]), "+f"(d[2]), "+f"(d[3])
        : "r"(a[0]), "r"(a[1]), "r"(a[2]), "r"(a[3]), "r"(b0), "r"(b1));
}
__device__ __forceinline__ void cp16(uint32_t sa, const void* ga) {
    asm volatile("cp.async.cg.shared.global [%0], [%1], 16;" :: "r"(sa), "l"(ga));
}
#define CP_COMMIT() asm volatile("cp.async.commit_group;" ::: "memory")
#define CP_WAIT(n)  asm volatile("cp.async.wait_group %0;" :: "n"(n) : "memory")

// load a [128 x 64] bf16 tile (row stride ld) into swizzled SMEM via cp.async
__device__ __forceinline__ void load_tile_async(const __nv_bfloat16* __restrict__ src,
                                                size_t ld, uint32_t sbase, int tid) {
#pragma unroll
    for (int t = 0; t < 4; t++) {
        int i = tid + t * 256;
        int row = i >> 3, c = i & 7;
        cp16(sbase + SWZ(row * 128 + c * 16), src + (size_t)row * ld + c * 8);
    }
}

// ------------- 128x128-tile bf16 HMMA GEMM, fp32 accum -------------
// D[m0:+128, n0:+128] = A[m,:] @ B[n,:]^T   (A: MxK k-major; B: NxK k-major)
// MODE 0: bf16 out + fp32 bias; MODE 1: bf16 out; MODE 2: fp32 out = X + sig*(D+bias)
template <int MODE>
__global__ void __launch_bounds__(256, 2)
gemm128(const __nv_bfloat16* __restrict__ A, int lda,
        const __nv_bfloat16* __restrict__ B, int ldb, size_t bstride,
        int K,
        __nv_bfloat16* __restrict__ outb, int ldo,
        const float* __restrict__ bias,
        const float* __restrict__ Xres, const float* __restrict__ sig,
        float* __restrict__ outf) {
    extern __shared__ char sm[];
    uint32_t base = smem_u32(sm);
    const uint32_t a_su[2] = {base, base + 16384};
    const uint32_t b_su[2] = {base + 32768, base + 49152};

    int tid = threadIdx.x, wid = tid >> 5, lane = tid & 31;
    int m0 = blockIdx.y * 128, n0 = blockIdx.x * 128;
    int wm = wid & 3, wn = wid >> 2;
    int lr = lane & 15, lc = lane >> 4;

    const __nv_bfloat16* Ab = A + (size_t)m0 * lda;
    const __nv_bfloat16* Bb = B + (size_t)(m0 >> 12) * bstride + (size_t)n0 * ldb;

    float acc[2][8][4];
#pragma unroll
    for (int i = 0; i < 2; i++)
#pragma unroll
        for (int j = 0; j < 8; j++)
#pragma unroll
            for (int e = 0; e < 4; e++) acc[i][j][e] = 0.f;

    const int nc = K >> 6;
    load_tile_async(Ab, (size_t)lda, a_su[0], tid);
    load_tile_async(Bb, (size_t)ldb, b_su[0], tid);
    CP_COMMIT();

    for (int c = 0; c < nc; c++) {
        if (c + 1 < nc) {
            int nb = (c + 1) & 1;
            load_tile_async(Ab + (c + 1) * 64, (size_t)lda, a_su[nb], tid);
            load_tile_async(Bb + (c + 1) * 64, (size_t)ldb, b_su[nb], tid);
            CP_COMMIT();
            CP_WAIT(1);
        } else {
            CP_WAIT(0);
        }
        __syncthreads();

        uint32_t abase = a_su[c & 1], bbase = b_su[c & 1];
#pragma unroll
        for (int k16 = 0; k16 < 4; k16++) {
            uint32_t af[2][4];
#pragma unroll
            for (int mt = 0; mt < 2; mt++)
                ldsm_x4(af[mt], abase + SWZ((wm * 32 + mt * 16 + lr) * 128 + k16 * 32 + lc * 16));
            uint32_t bf4[4][4];
#pragma unroll
            for (int nt2 = 0; nt2 < 4; nt2++)
                ldsm_x4(bf4[nt2], bbase + SWZ((wn * 64 + nt2 * 16 + lr) * 128 + k16 * 32 + lc * 16));
#pragma unroll
            for (int mt = 0; mt < 2; mt++)
#pragma unroll
                for (int nt = 0; nt < 8; nt++)
                    mma16816(acc[mt][nt], af[mt], bf4[nt >> 1][nt & 1], bf4[nt >> 1][2 + (nt & 1)]);
        }
        __syncthreads();
    }

    // epilogue
    int r0 = m0 + wm * 32 + (lane >> 2);
    int c0 = n0 + wn * 64 + (lane & 3) * 2;
    float s = 0.f;
    if (MODE == 2) s = sig[0];
#pragma unroll
    for (int mt = 0; mt < 2; mt++) {
#pragma unroll
        for (int half = 0; half < 2; half++) {
            int row = r0 + mt * 16 + half * 8;
#pragma unroll
            for (int nt = 0; nt < 8; nt++) {
                int col = c0 + nt * 8;
                float v0 = acc[mt][nt][half * 2 + 0];
                float v1 = acc[mt][nt][half * 2 + 1];
                if (MODE == 0) { v0 += bias[col]; v1 += bias[col + 1]; }
                if (MODE == 2) {
                    const float* xr = Xres + (size_t)row * CCH + col;
                    float2 xv = *(const float2*)xr;
                    float2 o;
                    o.x = xv.x + s * (v0 + bias[col]);
                    o.y = xv.y + s * (v1 + bias[col + 1]);
                    *(float2*)(outf + (size_t)row * CCH + col) = o;
                } else {
                    *(__nv_bfloat162*)(outb + (size_t)row * ldo + col) =
                        __floats2bfloat162_rn(v0, v1);
                }
            }
        }
    }
}

// ---------------- small kernels ----------------
__global__ void pack_kernel(const float* __restrict__ wt, const float* __restrict__ wp,
                            const float* __restrict__ wg, const float* __restrict__ bt,
                            const float* __restrict__ bp, const float* __restrict__ bg,
                            const float* __restrict__ wo) {
    int idx = blockIdx.x * blockDim.x + threadIdx.x;
    if (idx < NPROJ * CCH) {           // wcatT[n][k] = w(k, n)
        int n = idx / CCH, k = idx - n * CCH;
        float v;
        if (n < 64)       v = wt[k * 64 + n];
        else if (n < 128) v = wp[k * 64 + (n - 64)];
        else              v = wg[k * 256 + (n - 128)];
        g_wcatT[idx] = __float2bfloat16(v);
    }
    if (idx < CCH * DV) {              // woT[n][k] = wo[k][n]
        int n = idx / DV, k = idx - n * DV;
        g_woT[idx] = __float2bfloat16(wo[k * CCH + n]);
    }
    if (idx < NPROJ) {
        float v;
        if (idx < 64)       v = bt[idx];
        else if (idx < 128) v = bp[idx - 64];
        else                v = bg[idx - 128];
        g_bcat[idx] = v;
    }
}

__global__ void xconv_kernel(const float* __restrict__ x) {
    int i = blockIdx.x * blockDim.x + threadIdx.x;  // 8 elems each
    if (i >= M_PIX * CCH / 8) return;
    float4 a = *(const float4*)(x + (size_t)i * 8);
    float4 b = *(const float4*)(x + (size_t)i * 8 + 4);
    __nv_bfloat162 h[4];
    h[0] = __floats2bfloat162_rn(a.x, a.y);
    h[1] = __floats2bfloat162_rn(a.z, a.w);
    h[2] = __floats2bfloat162_rn(b.x, b.y);
    h[3] = __floats2bfloat162_rn(b.z, b.w);
    *(uint4*)(g_xb + (size_t)i * 8) = *(uint4*)h;
}

__global__ void pool_phi_kernel() {
    int i = blockIdx.x * blockDim.x + threadIdx.x;
    if (i >= BBATCH * NKV * 8) return;   // 8 groups of 8 channels
    int pp = i >> 3, c8 = i & 7;
    int b = pp >> 10, idx = pp & 1023;
    int h2 = idx >> 5, w2 = idx & 31;
    size_t p = (size_t)((b * 64 + h2 * 2) * 64 + w2 * 2);
    const __nv_bfloat16* src = g_projb + p * NPROJ + 64 + c8 * 8;
    uint4 u0 = *(const uint4*)(src);
    uint4 u1 = *(const uint4*)(src + NPROJ);
    uint4 u2 = *(const uint4*)(src + 64 * NPROJ);
    uint4 u3 = *(const uint4*)(src + 65 * NPROJ);
    __nv_bfloat162* h0 = (__nv_bfloat162*)&u0; __nv_bfloat162* h1 = (__nv_bfloat162*)&u1;
    __nv_bfloat162* h2v = (__nv_bfloat162*)&u2; __nv_bfloat162* h3 = (__nv_bfloat162*)&u3;
    __nv_bfloat162 o[4];
#pragma unroll
    for (int j = 0; j < 4; j++)
        o[j] = __hmax2(__hmax2(h0[j], h1[j]), __hmax2(h2v[j], h3[j]));
    *(uint4*)(g_phi + (size_t)pp * DK + c8 * 8) = *(uint4*)o;
}

__global__ void pool_gt_kernel() {   // pooled g, transposed to [b][d][kv]
    __shared__ __nv_bfloat16 ts[64][65];
    int tid = threadIdx.x;
    int d0 = blockIdx.x * 64, kv0 = blockIdx.y * 64, b = blockIdx.z;
#pragma unroll
    for (int e = 0; e < 16; e++) {
        int idx = tid + e * 256;
        int kvl = idx >> 6, dl = idx & 63;
        int kv = kv0 + kvl;
        int h2 = kv >> 5, w2 = kv & 31;
        size_t p = (size_t)((b * 64 + h2 * 2) * 64 + w2 * 2);
        const __nv_bfloat16* src = g_projb + p * NPROJ + 128 + d0 + dl;
        __nv_bfloat16 v = __hmax(__hmax(src[0], src[NPROJ]),
                                 __hmax(src[64 * NPROJ], src[65 * NPROJ]));
        ts[kvl][dl] = v;
    }
    __syncthreads();
#pragma unroll
    for (int e = 0; e < 16; e++) {
        int idx = tid + e * 256;
        int dl = idx >> 6, kk = idx & 63;
        g_gT[((size_t)b * DV + d0 + dl) * NKV + kv0 + kk] = ts[kk][dl];
    }
}

__global__ void __launch_bounds__(256) softmax_kernel() {  // in-place on g_S rows
    size_t row = (size_t)blockIdx.x * 8 + (threadIdx.x >> 5);
    int lane = threadIdx.x & 31;
    __nv_bfloat16* p = g_S + row * NKV;
    float v[32];
#pragma unroll
    for (int s = 0; s < 4; s++) {
        uint4 u = *(const uint4*)(p + s * 256 + lane * 8);
        __nv_bfloat162* h = (__nv_bfloat162*)&u;
#pragma unroll
        for (int j = 0; j < 4; j++) {
            float2 f = __bfloat1622float2(h[j]);
            v[s * 8 + 2 * j] = f.x; v[s * 8 + 2 * j + 1] = f.y;
        }
    }
    float mx = v[0];
#pragma unroll
    for (int j = 1; j < 32; j++) mx = fmaxf(mx, v[j]);
#pragma unroll
    for (int o = 16; o > 0; o >>= 1) mx = fmaxf(mx, __shfl_xor_sync(0xffffffffu, mx, o));
    float sum = 0.f;
#pragma unroll
    for (int j = 0; j < 32; j++) { v[j] = __expf(v[j] - mx); sum += v[j]; }
#pragma unroll
    for (int o = 16; o > 0; o >>= 1) sum += __shfl_xor_sync(0xffffffffu, sum, o);
    float inv = 1.f / sum;
#pragma unroll
    for (int s = 0; s < 4; s++) {
        __nv_bfloat162 h[4];
#pragma unroll
        for (int j = 0; j < 4; j++)
            h[j] = __floats2bfloat162_rn(v[s * 8 + 2 * j] * inv, v[s * 8 + 2 * j + 1] * inv);
        *(uint4*)(p + s * 256 + lane * 8) = *(uint4*)h;
    }
}

// ---------------- launcher ----------------
extern "C" void kernel_launch(void* const* d_in, const int* in_sizes, int n_in,
                              void* d_out, int out_size) {
    const float* x       = (const float*)d_in[0];
    const float* w_theta = (const float*)d_in[1];
    const float* b_theta = (const float*)d_in[2];
    const float* w_phi   = (const float*)d_in[3];
    const float* b_phi   = (const float*)d_in[4];
    const float* w_g     = (const float*)d_in[5];
    const float* b_g     = (const float*)d_in[6];
    const float* w_o     = (const float*)d_in[7];
    const float* b_o     = (const float*)d_in[8];
    const float* sigma   = (const float*)d_in[9];
    float* out = (float*)d_out;

    const int SMEM = 65536;
    cudaFuncSetAttribute((const void*)gemm128<0>, cudaFuncAttributeMaxDynamicSharedMemorySize, SMEM);
    cudaFuncSetAttribute((const void*)gemm128<1>, cudaFuncAttributeMaxDynamicSharedMemorySize, SMEM);
    cudaFuncSetAttribute((const void*)gemm128<2>, cudaFuncAttributeMaxDynamicSharedMemorySize, SMEM);

    __nv_bfloat16 *xb, *projb, *phi, *gT, *S, *ag, *wcatT, *woT;
    float* bcat;
    cudaGetSymbolAddress((void**)&xb, g_xb);       cudaGetSymbolAddress((void**)&projb, g_projb);
    cudaGetSymbolAddress((void**)&phi, g_phi);     cudaGetSymbolAddress((void**)&gT, g_gT);
    cudaGetSymbolAddress((void**)&S, g_S);         cudaGetSymbolAddress((void**)&ag, g_ag);
    cudaGetSymbolAddress((void**)&wcatT, g_wcatT); cudaGetSymbolAddress((void**)&woT, g_woT);
    cudaGetSymbolAddress((void**)&bcat, g_bcat);

    pack_kernel<<<(NPROJ * CCH + 255) / 256, 256>>>(w_theta, w_phi, w_g,
                                                    b_theta, b_phi, b_g, w_o);
    xconv_kernel<<<M_PIX * CCH / 8 / 256, 256>>>(x);

    // proj: [65536, 384] = xb[65536,512] @ wcatT[384,512]^T, +bias
    gemm128<0><<<dim3(NPROJ / 128, M_PIX / 128), 256, SMEM>>>(
        xb, CCH, wcatT, CCH, 0, CCH, projb, NPROJ, bcat, nullptr, nullptr, nullptr);

    pool_phi_kernel<<<(BBATCH * NKV * 8 + 255) / 256, 256>>>();
    pool_gt_kernel<<<dim3(DV / 64, NKV / 64, BBATCH), 256>>>();

    // S: per batch [4096, 1024] = theta[4096,64] @ phi[1024,64]^T
    gemm128<1><<<dim3(NKV / 128, M_PIX / 128), 256, SMEM>>>(
        projb, NPROJ, phi, DK, (size_t)NKV * DK, DK, S, NKV, nullptr, nullptr, nullptr, nullptr);

    softmax_kernel<<<M_PIX / 8, 256>>>();

    // PV: per batch [4096, 256] = P[4096,1024] @ gT[256,1024]^T
    gemm128<1><<<dim3(DV / 128, M_PIX / 128), 256, SMEM>>>(
        S, NKV, gT, NKV, (size_t)DV * NKV, NKV, ag, DV, nullptr, nullptr, nullptr, nullptr);

    // out: [65536, 512] = x + sigma * (ag[65536,256] @ woT[512,256]^T + b_o)
    gemm128<2><<<dim3(CCH / 128, M_PIX / 128), 256, SMEM>>>(
        ag, DV, woT, DV, 0, DV, nullptr, 0, b_o, x, sigma, out);
}

// round 4
// speedup vs baseline: 6.4701x; 1.0718x over previous
#include <cuda_runtime.h>
#include <cuda_bf16.h>
#include <cstdint>

#define BBATCH 16
#define CCH 512
#define M_PIX (BBATCH*64*64)     // 65536
#define NPROJ 384
#define DK 64
#define DV 256
#define NKV 1024
#define NQ  4096

// ---------------- scratch (device globals) ----------------
__device__ __align__(256) __nv_bfloat16 g_xb   [M_PIX * CCH];       // x in bf16
__device__ __align__(256) __nv_bfloat16 g_projb[M_PIX * NPROJ];     // theta|phi|g bf16
__device__ __align__(256) __nv_bfloat16 g_phi  [BBATCH * NKV * DK]; // pooled phi [kv][d]
__device__ __align__(256) __nv_bfloat16 g_gT   [BBATCH * DV * NKV]; // pooled g^T [d][kv]
__device__ __align__(256) __nv_bfloat16 g_S    [(size_t)M_PIX * NKV]; // exp(logits)
__device__ __align__(256) __nv_bfloat16 g_ag   [M_PIX * DV];        // attn out bf16
__device__ __align__(256) __nv_bfloat16 g_wcatT[NPROJ * CCH];       // proj weights^T
__device__ __align__(256) __nv_bfloat16 g_woT  [CCH * DV];          // w_o^T
__device__ float g_bcat[NPROJ];

// ---------------- helpers ----------------
__device__ __forceinline__ uint32_t smem_u32(const void* p) {
    uint32_t a;
    asm("{ .reg .u64 t; cvta.to.shared.u64 t, %1; cvt.u32.u64 %0, t; }" : "=r"(a) : "l"(p));
    return a;
}
#define SWZ(o) ((o) ^ (((o) >> 3) & 0x70))

__device__ __forceinline__ void ldsm_x4(uint32_t* r, uint32_t a) {
    asm volatile("ldmatrix.sync.aligned.m8n8.x4.shared.b16 {%0,%1,%2,%3}, [%4];"
        : "=r"(r[0]), "=r"(r[1]), "=r"(r[2]), "=r"(r[3]) : "r"(a));
}
__device__ __forceinline__ void mma16816(float* d, const uint32_t* a, uint32_t b0, uint32_t b1) {
    asm volatile("mma.sync.aligned.m16n8k16.row.col.f32.bf16.bf16.f32 "
        "{%0,%1,%2,%3}, {%4,%5,%6,%7}, {%8,%9}, {%0,%1,%2,%3};"
        : "+f"(d[0]), "+f"(d[1]), "+f"(d[2]), "+f"(d[3])
        : "r"(a[0]), "r"(a[1]), "r"(a[2]), "r"(a[3]), "r"(b0), "r"(b1));
}
__device__ __forceinline__ void cp16(uint32_t sa, const void* ga) {
    asm volatile("cp.async.cg.shared.global [%0], [%1], 16;" :: "r"(sa), "l"(ga));
}
#define CP_COMMIT() asm volatile("cp.async.commit_group;" ::: "memory")
#define CP_WAIT(n)  asm volatile("cp.async.wait_group %0;" :: "n"(n) : "memory")

// load a [128 x 64] bf16 tile (row stride ld) into swizzled SMEM via cp.async
__device__ __forceinline__ void load_tile_async(const __nv_bfloat16* __restrict__ src,
                                                size_t ld, uint32_t sbase, int tid) {
#pragma unroll
    for (int t = 0; t < 4; t++) {
        int i = tid + t * 256;
        int row = i >> 3, c = i & 7;
        cp16(sbase + SWZ(row * 128 + c * 16), src + (size_t)row * ld + c * 8);
    }
}

// ------------- 128x128-tile bf16 HMMA GEMM, fp32 accum, 3-stage cp.async ----
// D[m0:+128, n0:+128] = A[m,:] @ B[n,:]^T   (A: MxK k-major; B: NxK k-major)
// MODE 0: bf16 out + fp32 bias
// MODE 2: fp32 out = X + sig*(D+bias)
// MODE 3: bf16 out, normalized by row sums of A (computed in-loop)   [PV]
// MODE 4: bf16 out = exp(D)                                          [S]
template <int MODE>
__global__ void __launch_bounds__(256, 2)
gemm128(const __nv_bfloat16* __restrict__ A, int lda,
        const __nv_bfloat16* __restrict__ B, int ldb, size_t bstride,
        int K,
        __nv_bfloat16* __restrict__ outb, int ldo,
        const float* __restrict__ bias,
        const float* __restrict__ Xres, const float* __restrict__ sig,
        float* __restrict__ outf) {
    extern __shared__ char sm[];
    uint32_t base = smem_u32(sm);
    const uint32_t a_su[3] = {base, base + 16384, base + 32768};
    const uint32_t b_su[3] = {base + 49152, base + 65536, base + 81920};
    float* rinv_s = (float*)(sm + 98304);   // [128] (MODE 3)

    int tid = threadIdx.x, wid = tid >> 5, lane = tid & 31;
    int m0 = blockIdx.y * 128, n0 = blockIdx.x * 128;
    int wm = wid & 3, wn = wid >> 2;
    int lr = lane & 15, lc = lane >> 4;

    const __nv_bfloat16* Ab = A + (size_t)m0 * lda;
    const __nv_bfloat16* Bb = B + (size_t)(m0 >> 12) * bstride + (size_t)n0 * ldb;

    float acc[2][8][4];
#pragma unroll
    for (int i = 0; i < 2; i++)
#pragma unroll
        for (int j = 0; j < 8; j++)
#pragma unroll
            for (int e = 0; e < 4; e++) acc[i][j][e] = 0.f;

    float rsum = 0.f;
    const int nc = K >> 6;

    // prologue: prefetch chunks 0 and 1 (separate groups)
    load_tile_async(Ab, (size_t)lda, a_su[0], tid);
    load_tile_async(Bb, (size_t)ldb, b_su[0], tid);
    CP_COMMIT();
    if (nc > 1) {
        load_tile_async(Ab + 64, (size_t)lda, a_su[1], tid);
        load_tile_async(Bb + 64, (size_t)ldb, b_su[1], tid);
        CP_COMMIT();
    }

    for (int c = 0; c < nc; c++) {
        if (c + 2 <= nc) { CP_WAIT(1); } else { CP_WAIT(0); }
        __syncthreads();

        int buf = c % 3;
        if (MODE == 3) {
            // accumulate row sums of exp(S) from the A chunk (deterministic order)
            int row = tid >> 1, half = tid & 1;
            const char* aptr = sm + buf * 16384;
#pragma unroll
            for (int c8 = 0; c8 < 4; c8++) {
                uint4 u = *(const uint4*)(aptr + SWZ(row * 128 + half * 64 + c8 * 16));
                const __nv_bfloat162* h = (const __nv_bfloat162*)&u;
#pragma unroll
                for (int j = 0; j < 4; j++) {
                    float2 f = __bfloat1622float2(h[j]);
                    rsum += f.x + f.y;
                }
            }
        }

        uint32_t abase = a_su[buf], bbase = b_su[buf];
#pragma unroll
        for (int k16 = 0; k16 < 4; k16++) {
            uint32_t af[2][4];
#pragma unroll
            for (int mt = 0; mt < 2; mt++)
                ldsm_x4(af[mt], abase + SWZ((wm * 32 + mt * 16 + lr) * 128 + k16 * 32 + lc * 16));
            uint32_t bf4[4][4];
#pragma unroll
            for (int nt2 = 0; nt2 < 4; nt2++)
                ldsm_x4(bf4[nt2], bbase + SWZ((wn * 64 + nt2 * 16 + lr) * 128 + k16 * 32 + lc * 16));
#pragma unroll
            for (int mt = 0; mt < 2; mt++)
#pragma unroll
                for (int nt = 0; nt < 8; nt++)
                    mma16816(acc[mt][nt], af[mt], bf4[nt >> 1][nt & 1], bf4[nt >> 1][2 + (nt & 1)]);
        }

        if (c + 2 < nc) {
            int nb = (c + 2) % 3;
            load_tile_async(Ab + (c + 2) * 64, (size_t)lda, a_su[nb], tid);
            load_tile_async(Bb + (c + 2) * 64, (size_t)ldb, b_su[nb], tid);
            CP_COMMIT();
        }
    }

    if (MODE == 3) {
        rsum += __shfl_xor_sync(0xffffffffu, rsum, 1);
        if ((tid & 1) == 0) rinv_s[tid >> 1] = 1.f / rsum;
        __syncthreads();
    }

    // epilogue
    int r0 = m0 + wm * 32 + (lane >> 2);
    int c0 = n0 + wn * 64 + (lane & 3) * 2;
    float s = 0.f;
    if (MODE == 2) s = sig[0];
#pragma unroll
    for (int mt = 0; mt < 2; mt++) {
#pragma unroll
        for (int half = 0; half < 2; half++) {
            int row = r0 + mt * 16 + half * 8;
            float rscale = 1.f;
            if (MODE == 3) rscale = rinv_s[wm * 32 + (lane >> 2) + mt * 16 + half * 8];
#pragma unroll
            for (int nt = 0; nt < 8; nt++) {
                int col = c0 + nt * 8;
                float v0 = acc[mt][nt][half * 2 + 0];
                float v1 = acc[mt][nt][half * 2 + 1];
                if (MODE == 0) { v0 += bias[col]; v1 += bias[col + 1]; }
                if (MODE == 3) { v0 *= rscale; v1 *= rscale; }
                if (MODE == 4) { v0 = __expf(v0); v1 = __expf(v1); }
                if (MODE == 2) {
                    const float* xr = Xres + (size_t)row * CCH + col;
                    float2 xv = *(const float2*)xr;
                    float2 o;
                    o.x = xv.x + s * (v0 + bias[col]);
                    o.y = xv.y + s * (v1 + bias[col + 1]);
                    *(float2*)(outf + (size_t)row * CCH + col) = o;
                } else {
                    *(__nv_bfloat162*)(outb + (size_t)row * ldo + col) =
                        __floats2bfloat162_rn(v0, v1);
                }
            }
        }
    }
}

// ---------------- small kernels ----------------
__global__ void pack_kernel(const float* __restrict__ wt, const float* __restrict__ wp,
                            const float* __restrict__ wg, const float* __restrict__ bt,
                            const float* __restrict__ bp, const float* __restrict__ bg,
                            const float* __restrict__ wo) {
    int idx = blockIdx.x * blockDim.x + threadIdx.x;
    if (idx < NPROJ * CCH) {           // wcatT[n][k] = w(k, n)
        int n = idx / CCH, k = idx - n * CCH;
        float v;
        if (n < 64)       v = wt[k * 64 + n];
        else if (n < 128) v = wp[k * 64 + (n - 64)];
        else              v = wg[k * 256 + (n - 128)];
        g_wcatT[idx] = __float2bfloat16(v);
    }
    if (idx < CCH * DV) {              // woT[n][k] = wo[k][n]
        int n = idx / DV, k = idx - n * DV;
        g_woT[idx] = __float2bfloat16(wo[k * CCH + n]);
    }
    if (idx < NPROJ) {
        float v;
        if (idx < 64)       v = bt[idx];
        else if (idx < 128) v = bp[idx - 64];
        else                v = bg[idx - 128];
        g_bcat[idx] = v;
    }
}

__global__ void xconv_kernel(const float* __restrict__ x) {
    int i = blockIdx.x * blockDim.x + threadIdx.x;  // 8 elems each
    if (i >= M_PIX * CCH / 8) return;
    float4 a = *(const float4*)(x + (size_t)i * 8);
    float4 b = *(const float4*)(x + (size_t)i * 8 + 4);
    __nv_bfloat162 h[4];
    h[0] = __floats2bfloat162_rn(a.x, a.y);
    h[1] = __floats2bfloat162_rn(a.z, a.w);
    h[2] = __floats2bfloat162_rn(b.x, b.y);
    h[3] = __floats2bfloat162_rn(b.z, b.w);
    *(uint4*)(g_xb + (size_t)i * 8) = *(uint4*)h;
}

__global__ void pool_phi_kernel() {
    int i = blockIdx.x * blockDim.x + threadIdx.x;
    if (i >= BBATCH * NKV * 8) return;   // 8 groups of 8 channels
    int pp = i >> 3, c8 = i & 7;
    int b = pp >> 10, idx = pp & 1023;
    int h2 = idx >> 5, w2 = idx & 31;
    size_t p = (size_t)((b * 64 + h2 * 2) * 64 + w2 * 2);
    const __nv_bfloat16* src = g_projb + p * NPROJ + 64 + c8 * 8;
    uint4 u0 = *(const uint4*)(src);
    uint4 u1 = *(const uint4*)(src + NPROJ);
    uint4 u2 = *(const uint4*)(src + 64 * NPROJ);
    uint4 u3 = *(const uint4*)(src + 65 * NPROJ);
    __nv_bfloat162* h0 = (__nv_bfloat162*)&u0; __nv_bfloat162* h1 = (__nv_bfloat162*)&u1;
    __nv_bfloat162* h2v = (__nv_bfloat162*)&u2; __nv_bfloat162* h3 = (__nv_bfloat162*)&u3;
    __nv_bfloat162 o[4];
#pragma unroll
    for (int j = 0; j < 4; j++)
        o[j] = __hmax2(__hmax2(h0[j], h1[j]), __hmax2(h2v[j], h3[j]));
    *(uint4*)(g_phi + (size_t)pp * DK + c8 * 8) = *(uint4*)o;
}

__global__ void pool_gt_kernel() {   // pooled g, transposed to [b][d][kv]
    __shared__ __nv_bfloat16 ts[64][65];
    int tid = threadIdx.x;
    int d0 = blockIdx.x * 64, kv0 = blockIdx.y * 64, b = blockIdx.z;
#pragma unroll
    for (int e = 0; e < 16; e++) {
        int idx = tid + e * 256;
        int kvl = idx >> 6, dl = idx & 63;
        int kv = kv0 + kvl;
        int h2 = kv >> 5, w2 = kv & 31;
        size_t p = (size_t)((b * 64 + h2 * 2) * 64 + w2 * 2);
        const __nv_bfloat16* src = g_projb + p * NPROJ + 128 + d0 + dl;
        __nv_bfloat16 v = __hmax(__hmax(src[0], src[NPROJ]),
                                 __hmax(src[64 * NPROJ], src[65 * NPROJ]));
        ts[kvl][dl] = v;
    }
    __syncthreads();
#pragma unroll
    for (int e = 0; e < 16; e++) {
        int idx = tid + e * 256;
        int dl = idx >> 6, kk = idx & 63;
        g_gT[((size_t)b * DV + d0 + dl) * NKV + kv0 + kk] = ts[kk][dl];
    }
}

// ---------------- launcher ----------------
extern "C" void kernel_launch(void* const* d_in, const int* in_sizes, int n_in,
                              void* d_out, int out_size) {
    const float* x       = (const float*)d_in[0];
    const float* w_theta = (const float*)d_in[1];
    const float* b_theta = (const float*)d_in[2];
    const float* w_phi   = (const float*)d_in[3];
    const float* b_phi   = (const float*)d_in[4];
    const float* w_g     = (const float*)d_in[5];
    const float* b_g     = (const float*)d_in[6];
    const float* w_o     = (const float*)d_in[7];
    const float* b_o     = (const float*)d_in[8];
    const float* sigma   = (const float*)d_in[9];
    float* out = (float*)d_out;

    const int SMEM = 98304 + 512;
    cudaFuncSetAttribute((const void*)gemm128<0>, cudaFuncAttributeMaxDynamicSharedMemorySize, SMEM);
    cudaFuncSetAttribute((const void*)gemm128<2>, cudaFuncAttributeMaxDynamicSharedMemorySize, SMEM);
    cudaFuncSetAttribute((const void*)gemm128<3>, cudaFuncAttributeMaxDynamicSharedMemorySize, SMEM);
    cudaFuncSetAttribute((const void*)gemm128<4>, cudaFuncAttributeMaxDynamicSharedMemorySize, SMEM);

    __nv_bfloat16 *xb, *projb, *phi, *gT, *S, *ag, *wcatT, *woT;
    float* bcat;
    cudaGetSymbolAddress((void**)&xb, g_xb);       cudaGetSymbolAddress((void**)&projb, g_projb);
    cudaGetSymbolAddress((void**)&phi, g_phi);     cudaGetSymbolAddress((void**)&gT, g_gT);
    cudaGetSymbolAddress((void**)&S, g_S);         cudaGetSymbolAddress((void**)&ag, g_ag);
    cudaGetSymbolAddress((void**)&wcatT, g_wcatT); cudaGetSymbolAddress((void**)&woT, g_woT);
    cudaGetSymbolAddress((void**)&bcat, g_bcat);

    pack_kernel<<<(NPROJ * CCH + 255) / 256, 256>>>(w_theta, w_phi, w_g,
                                                    b_theta, b_phi, b_g, w_o);
    xconv_kernel<<<M_PIX * CCH / 8 / 256, 256>>>(x);

    // proj: [65536, 384] = xb[65536,512] @ wcatT[384,512]^T, +bias
    gemm128<0><<<dim3(NPROJ / 128, M_PIX / 128), 256, SMEM>>>(
        xb, CCH, wcatT, CCH, 0, CCH, projb, NPROJ, bcat, nullptr, nullptr, nullptr);

    pool_phi_kernel<<<(BBATCH * NKV * 8 + 255) / 256, 256>>>();
    pool_gt_kernel<<<dim3(DV / 64, NKV / 64, BBATCH), 256>>>();

    // S_exp: per batch [4096, 1024] = exp(theta[4096,64] @ phi[1024,64]^T)
    gemm128<4><<<dim3(NKV / 128, M_PIX / 128), 256, SMEM>>>(
        projb, NPROJ, phi, DK, (size_t)NKV * DK, DK, S, NKV, nullptr, nullptr, nullptr, nullptr);

    // PV: per batch [4096, 256] = (S_exp/rowsum)[4096,1024] @ gT[256,1024]^T
    gemm128<3><<<dim3(DV / 128, M_PIX / 128), 256, SMEM>>>(
        S, NKV, gT, NKV, (size_t)DV * NKV, NKV, ag, DV, nullptr, nullptr, nullptr, nullptr);

    // out: [65536, 512] = x + sigma * (ag[65536,256] @ woT[512,256]^T + b_o)
    gemm128<2><<<dim3(CCH / 128, M_PIX / 128), 256, SMEM>>>(
        ag, DV, woT, DV, 0, DV, nullptr, 0, b_o, x, sigma, out);
}